// round 9
// baseline (speedup 1.0000x reference)
#include <cuda_runtime.h>
#include <cuda_pipeline.h>
#include <math.h>

#define BB 64
#define PP 8732
#define CC 81
#define TPB 256
#define TILE 64                         // priors per tile
#define TX   ((PP + TILE - 1) / TILE)   // 137 tiles per batch row
#define NTILES (TX * BB)                // 8768
#define NPB  592                        // persistent blocks (4 per SM x 148)

// ---- smem layout (float offsets). Two tile buffers + aux ----
#define BUF_CONF 0                      // 64*81 = 5184
#define BUF_LOC  5184                   // 64 float4 = 256
#define BUF_LOCT 5440
#define BUF_FC   5696                   // 128 float4 = 512
#define BUF_FCT  6208
#define BUF_T    6720                   // 64 ints
#define BUF_SZ   6784                   // floats per buffer (27136 B)
#define OFF_PS   13568                  // 256
#define OFF_RL   13824
#define OFF_RF   13832
#define OFF_RC   13840
#define OFF_RP   13848
#define OFF_RN   13856
#define OFF_ISL  13864
#define OFF_NFB  13865
#define OFF_FBR  13866                  // 64
#define OFF_FIN  13930                  // 4 doubles (byte 55720, 8-aligned)
#define SMEM_FLOATS 13938
#define SMEM_BYTES  (SMEM_FLOATS * 4)   // 55752

// ---- device scratch (no allocations allowed) ----
__device__ double d_loss_l, d_loss_fc;
__device__ double d_ce_all[BB], d_ce_pos[BB];
__device__ int    d_numpos[BB];
__device__ double d_rowC[BB];
__device__ float  d_ce_row[PP];
__device__ int    d_done;

__global__ void k_init() {
    int i = threadIdx.x;
    if (i == 0) { d_loss_l = 0.0; d_loss_fc = 0.0; d_done = 0; }
    if (i < BB) { d_ce_all[i] = 0.0; d_ce_pos[i] = 0.0; d_numpos[i] = 0; d_rowC[i] = 0.0; }
}

// issue all cp.async loads for one tile into a buffer, then commit.
__device__ __forceinline__ void issue_tile(
    float* sm, int bufbase, int tile, int tid,
    const float* loc_data, const float* conf, const float* fc_data,
    const float* loc_t, const float* fc_t, const int* conf_t)
{
    if (tile < NTILES) {
        const int b  = tile / TX;
        const int p0 = (tile - b * TX) * TILE;
        const int nloc = (PP - p0 < TILE) ? (PP - p0) : TILE;   // 64 or 28
        const unsigned rowp = (unsigned)(b * PP + p0);
        float4* dst = (float4*)(sm + bufbase + BUF_CONF);
        const float4* src = (const float4*)conf + (rowp * (unsigned)CC) / 4u;
        const int nvec = nloc * CC / 4;                          // 1296 or 567
        #pragma unroll 2
        for (int i = tid; i < nvec; i += TPB)
            __pipeline_memcpy_async(dst + i, src + i, 16);
        if (tid < nloc / 4)
            __pipeline_memcpy_async((float4*)(sm + bufbase + BUF_T) + tid,
                                    (const float4*)(conf_t + rowp) + tid, 16);
        if (tid < nloc) {
            __pipeline_memcpy_async((float4*)(sm + bufbase + BUF_LOC) + tid,
                                    (const float4*)loc_data + rowp + tid, 16);
            __pipeline_memcpy_async((float4*)(sm + bufbase + BUF_LOCT) + tid,
                                    (const float4*)loc_t + rowp + tid, 16);
        }
        if (tid < 2 * nloc) {
            __pipeline_memcpy_async((float4*)(sm + bufbase + BUF_FC) + tid,
                                    (const float4*)fc_data + rowp * 2u + tid, 16);
            __pipeline_memcpy_async((float4*)(sm + bufbase + BUF_FCT) + tid,
                                    (const float4*)fc_t + rowp * 2u + tid, 16);
        }
    }
    __pipeline_commit();                // unconditional: keeps commit counts aligned
}

__global__ __launch_bounds__(TPB) void k_fused(
    const float* __restrict__ loc_data, const float* __restrict__ conf,
    const float* __restrict__ fc_data,  const float* __restrict__ loc_t,
    const float* __restrict__ fc_t,     const int* __restrict__ conf_t,
    float* __restrict__ out)
{
    extern __shared__ float sm[];
    const int tid  = threadIdx.x;
    const int lane = tid & 31;
    const int warp = tid >> 5;
    const int bid  = blockIdx.x;

    float accL = 0.f, accF = 0.f;       // global sums: accumulate across tiles

    // prologue: fill both buffers
    issue_tile(sm, 0,      bid,        tid, loc_data, conf, fc_data, loc_t, fc_t, conf_t);
    issue_tile(sm, BUF_SZ, bid + NPB,  tid, loc_data, conf, fc_data, loc_t, fc_t, conf_t);

    int cur = 0;
    for (int tile = bid; tile < NTILES; tile += NPB) {
        const int base = cur ? BUF_SZ : 0;
        const int b    = tile / TX;
        const int p0   = (tile - b * TX) * TILE;
        const int nloc = (PP - p0 < TILE) ? (PP - p0) : TILE;

        __pipeline_wait_prior(1);       // this buffer has landed
        __syncthreads();

        // phase A: 4 threads per prior, exp-sum segments (20/20/20/21)
        {
            const int prior = tid & 63;
            const int q     = tid >> 6;
            float part = 0.f;
            if (prior < nloc) {
                const float* row = sm + base + BUF_CONF + prior * CC + q * 20;
                float a0 = 0.f, a1 = 0.f;
                #pragma unroll
                for (int c = 0; c < 20; c += 2) {
                    a0 += __expf(row[c]);
                    a1 += __expf(row[c + 1]);
                }
                if (q == 3) a0 += __expf(row[20]);      // element 80
                part = a0 + a1;
            }
            sm[OFF_PS + tid] = part;
        }
        __syncthreads();

        // phase B: per-prior ce + loc/fc (threads 0..63 only)
        float ces = 0.f, cep = 0.f;
        int   np = 0;
        if (tid < nloc) {
            float S = (sm[OFF_PS + tid] + sm[OFF_PS + 64 + tid])
                    + (sm[OFF_PS + 128 + tid] + sm[OFF_PS + 192 + tid]);
            int t = ((int*)(sm + base + BUF_T))[tid];
            float ce = __logf(S) - sm[base + BUF_CONF + tid * CC + t];
            ces = ce;
            if (t > 0) {
                cep = ce; np = 1;
                float4 a0 = ((float4*)(sm + base + BUF_LOC))[tid];
                float4 t0 = ((float4*)(sm + base + BUF_LOCT))[tid];
                float4 b0 = ((float4*)(sm + base + BUF_FC))[tid * 2];
                float4 u0 = ((float4*)(sm + base + BUF_FCT))[tid * 2];
                float4 b1 = ((float4*)(sm + base + BUF_FC))[tid * 2 + 1];
                float4 u1 = ((float4*)(sm + base + BUF_FCT))[tid * 2 + 1];
                float d;
                d = fabsf(a0.x - t0.x); accL += (d < 1.f) ? 0.5f*d*d : d - 0.5f;
                d = fabsf(a0.y - t0.y); accL += (d < 1.f) ? 0.5f*d*d : d - 0.5f;
                d = fabsf(a0.z - t0.z); accL += (d < 1.f) ? 0.5f*d*d : d - 0.5f;
                d = fabsf(a0.w - t0.w); accL += (d < 1.f) ? 0.5f*d*d : d - 0.5f;
                d = fabsf(b0.x - u0.x); accF += (d < 1.f) ? 0.5f*d*d : d - 0.5f;
                d = fabsf(b0.y - u0.y); accF += (d < 1.f) ? 0.5f*d*d : d - 0.5f;
                d = fabsf(b0.z - u0.z); accF += (d < 1.f) ? 0.5f*d*d : d - 0.5f;
                d = fabsf(b0.w - u0.w); accF += (d < 1.f) ? 0.5f*d*d : d - 0.5f;
                d = fabsf(b1.x - u1.x); accF += (d < 1.f) ? 0.5f*d*d : d - 0.5f;
                d = fabsf(b1.y - u1.y); accF += (d < 1.f) ? 0.5f*d*d : d - 0.5f;
                d = fabsf(b1.z - u1.z); accF += (d < 1.f) ? 0.5f*d*d : d - 0.5f;
                d = fabsf(b1.w - u1.w); accF += (d < 1.f) ? 0.5f*d*d : d - 0.5f;
            }
        }
        // per-row reduce (nonzero only in warps 0-1)
        if (warp < 2) {
            #pragma unroll
            for (int o = 16; o; o >>= 1) {
                ces += __shfl_xor_sync(0xffffffffu, ces, o);
                cep += __shfl_xor_sync(0xffffffffu, cep, o);
                np  += __shfl_xor_sync(0xffffffffu, np,  o);
            }
            if (lane == 0) {
                sm[OFF_RC + warp] = ces; sm[OFF_RP + warp] = cep;
                ((int*)(sm + OFF_RN))[warp] = np;
            }
        }
        __syncthreads();                // also frees the buffer for refill
        if (tid == 0) {
            atomicAdd(&d_ce_all[b], (double)(sm[OFF_RC] + sm[OFF_RC + 1]));
            atomicAdd(&d_ce_pos[b], (double)(sm[OFF_RP] + sm[OFF_RP + 1]));
            atomicAdd(&d_numpos[b], ((int*)(sm + OFF_RN))[0] + ((int*)(sm + OFF_RN))[1]);
        }
        // refill this buffer with tile + 2*NPB
        issue_tile(sm, base, tile + 2 * NPB, tid,
                   loc_data, conf, fc_data, loc_t, fc_t, conf_t);
        cur ^= 1;
    }

    // flush global L/F accumulators (one reduce per block)
    #pragma unroll
    for (int o = 16; o; o >>= 1) {
        accL += __shfl_xor_sync(0xffffffffu, accL, o);
        accF += __shfl_xor_sync(0xffffffffu, accF, o);
    }
    if (lane == 0) { sm[OFF_RL + warp] = accL; sm[OFF_RF + warp] = accF; }
    __syncthreads();
    if (tid == 0) {
        float L = 0.f, F = 0.f;
        #pragma unroll
        for (int w = 0; w < 8; ++w) { L += sm[OFF_RL + w]; F += sm[OFF_RF + w]; }
        atomicAdd(&d_loss_l,  (double)L);
        atomicAdd(&d_loss_fc, (double)F);
    }

    // ---- completion handshake: last block does mining + finalize ----
    int* s_isl = (int*)(sm + OFF_ISL);
    __threadfence();
    if (tid == 0) *s_isl = (atomicAdd(&d_done, 1) == NPB - 1);
    __syncthreads();
    if (!*s_isl) return;
    __threadfence();
    __pipeline_wait_prior(0);           // drain before overlaying buffers
    __syncthreads();

    int*    sh  = (int*)sm;             // overlay on buffer0
    double* shd = (double*)(sm + 256);
    int*    s_nfb = (int*)(sm + OFF_NFB);
    int*    s_fbr = (int*)(sm + OFF_FBR);
    double* s_fin = (double*)(sm + OFF_FIN);

    // per-row selection. fast path: num_neg >= #negatives -> row sum = all ce.
    if (tid == 0) *s_nfb = 0;
    __syncthreads();
    if (tid < BB) {
        int npb = d_numpos[tid];
        long k3 = 3L * (long)npb;
        int k = (k3 < (long)(PP - 1)) ? (int)k3 : (PP - 1);
        int nneg = PP - npb;
        if (k >= nneg)      d_rowC[tid] = d_ce_all[tid];
        else if (k <= 0)    d_rowC[tid] = d_ce_pos[tid];
        else { int s = atomicAdd(s_nfb, 1); s_fbr[s] = tid; }
    }
    __syncthreads();

    // exact fallback (never triggered on this data): recompute ce for the row,
    // then bit-bisection for the k-th largest negative ce.
    const int nfbv = *s_nfb;
    for (int fi = 0; fi < nfbv; ++fi) {
        int bb = s_fbr[fi];
        long rb = (long)bb * PP;
        for (int i = warp; i < PP; i += 8) {
            const long cb = (rb + i) * CC;
            float v0 = conf[cb + lane];
            float v1 = conf[cb + lane + 32];
            float v2 = (lane < CC - 64) ? conf[cb + lane + 64] : 0.f;
            float s = __expf(v0) + __expf(v1);
            if (lane < CC - 64) s += __expf(v2);
            #pragma unroll
            for (int o = 16; o; o >>= 1) s += __shfl_xor_sync(0xffffffffu, s, o);
            int t = conf_t[rb + i];
            float cand = (t < 32) ? v0 : (t < 64) ? v1 : v2;
            float gath = __shfl_sync(0xffffffffu, cand, t & 31);
            if (lane == 0) d_ce_row[i] = __logf(s) - gath;
        }
        __syncthreads();
        int npb = d_numpos[bb];
        long k3 = 3L * (long)npb;
        int k = (k3 < (long)(PP - 1)) ? (int)k3 : (PP - 1);
        unsigned lo = 0u, hi = 0x7f800000u;
        while (lo < hi) {
            unsigned mid = lo + (hi - lo + 1u) / 2u;
            int c = 0;
            for (int i = tid; i < PP; i += TPB)
                if (conf_t[rb + i] == 0 &&
                    __float_as_uint(fmaxf(d_ce_row[i], 0.f)) >= mid) c++;
            sh[tid] = c; __syncthreads();
            for (int s = TPB/2; s; s >>= 1) { if (tid < s) sh[tid] += sh[tid + s]; __syncthreads(); }
            int tot = sh[0]; __syncthreads();
            if (tot >= k) lo = mid; else hi = mid - 1u;
        }
        int c = 0; double su = 0.0;
        for (int i = tid; i < PP; i += TPB) {
            if (conf_t[rb + i] == 0) {
                float v = d_ce_row[i];
                if (__float_as_uint(fmaxf(v, 0.f)) > lo) { c++; su += (double)v; }
            }
        }
        sh[tid] = c; shd[tid] = su; __syncthreads();
        for (int s = TPB/2; s; s >>= 1) {
            if (tid < s) { sh[tid] += sh[tid + s]; shd[tid] += shd[tid + s]; }
            __syncthreads();
        }
        if (tid == 0)
            d_rowC[bb] = d_ce_pos[bb] + shd[0] + (double)(k - sh[0]) * (double)__uint_as_float(lo);
        __syncthreads();
    }

    // ---- finalize (parallel) ----
    double n = (tid < BB) ? (double)d_numpos[tid] : 0.0;
    double c = (tid < BB) ? d_rowC[tid] : 0.0;
    if (tid < 64) {
        #pragma unroll
        for (int o = 16; o; o >>= 1) {
            n += __shfl_xor_sync(0xffffffffu, n, o);
            c += __shfl_xor_sync(0xffffffffu, c, o);
        }
        if (lane == 0) { s_fin[(tid >> 5) * 2] = n; s_fin[(tid >> 5) * 2 + 1] = c; }
    }
    __syncthreads();
    if (tid == 0) {
        double N  = s_fin[0] + s_fin[2];
        double Cc = s_fin[1] + s_fin[3];
        out[0] = (float)(d_loss_l / N);
        out[1] = (float)(Cc / N);
        out[2] = (float)(d_loss_fc / N);
    }
}

extern "C" void kernel_launch(void* const* d_in, const int* in_sizes, int n_in,
                              void* d_out, int out_size) {
    const float* loc_data = (const float*)d_in[0];
    const float* conf     = (const float*)d_in[1];
    const float* fc_data  = (const float*)d_in[2];
    const float* loc_t    = (const float*)d_in[3];
    const float* fc_t     = (const float*)d_in[4];
    const int*   conf_t   = (const int*)d_in[5];

    cudaFuncSetAttribute(k_fused, cudaFuncAttributeMaxDynamicSharedMemorySize, SMEM_BYTES);
    k_init<<<1, 64>>>();
    k_fused<<<NPB, TPB, SMEM_BYTES>>>(loc_data, conf, fc_data, loc_t, fc_t, conf_t, (float*)d_out);
}